// round 1
// baseline (speedup 1.0000x reference)
#include <cuda_runtime.h>
#include <cstdint>

// ---------------- problem constants (from setup_inputs) ----------------
#define B       32
#define TSTEPS  8

// Layer sizes
#define C1_IN   3
#define C1_OUT  64
#define H1      32          // conv1/conv2 spatial
#define C2_OUT  128
#define H3      16          // conv3 spatial (after pool)
#define FC1_IN  8192        // 128*8*8
#define FC1_OUT 1024
#define FC2_OUT 10

// ---------------- device state / scratch (no allocations allowed) ------
__device__ float g_conv1out[B * C1_OUT * H1 * H1];    // 8 MB
__device__ float g_m1      [B * C1_OUT * H1 * H1];    // 8 MB
__device__ float g_s1      [B * C1_OUT * H1 * H1];    // 8 MB
__device__ float g_conv2out[B * C2_OUT * H1 * H1];    // 16 MB
__device__ float g_m2      [B * C2_OUT * H1 * H1];    // 16 MB
__device__ float g_s2p     [B * C2_OUT * H3 * H3];    // 4 MB
__device__ float g_conv3out[B * C2_OUT * H3 * H3];    // 4 MB
__device__ float g_m3      [B * C2_OUT * H3 * H3];    // 4 MB
__device__ float g_s3p     [B * FC1_IN];              // 1 MB
__device__ float g_part    [8 * B * FC1_OUT];         // 1 MB   fc1 split-k partials
__device__ float g_c1      [B * FC1_OUT];
__device__ float g_sfc1    [B * FC1_OUT];

// ---------------- generic 3x3 SAME conv ----------------
// Block: one (batch, 8-out-channel group), full HW x HW tile.
// Threads: (HW/2)^2, each computes a 2x2 pixel patch for 8 output channels.
// Input channels staged one at a time in smem; all-zero channels are skipped
// (spike inputs are mostly zero), which is an exact optimization.
template<int CIN, int HW>
__global__ void conv3x3_kernel(const float* __restrict__ in,
                               const float* __restrict__ wt,
                               const float* __restrict__ bias,
                               float* __restrict__ out,
                               int Cout)
{
    constexpr int TP  = HW / 2;          // threads per dim
    constexpr int NT  = TP * TP;         // threads per block
    constexpr int TW  = HW + 2;          // padded tile width
    constexpr int OCT = 8;

    const int b   = blockIdx.y;
    const int ocb = blockIdx.x * OCT;
    const int tid = threadIdx.x;
    const int ty  = (tid / TP) * 2;
    const int tx  = (tid % TP) * 2;

    __shared__ float tile[TW * TW];
    __shared__ float ws[OCT][9];

    float acc[OCT][4];
#pragma unroll
    for (int o = 0; o < OCT; ++o) { acc[o][0]=acc[o][1]=acc[o][2]=acc[o][3]=0.f; }

    const float* inb = in + (size_t)b * CIN * HW * HW;

    for (int ic = 0; ic < CIN; ++ic) {
        const float* src = inb + (size_t)ic * HW * HW;
        int nz = 0;
        // load padded input tile
        for (int i = tid; i < TW * TW; i += NT) {
            int r = i / TW - 1, c = i % TW - 1;
            float v = (r >= 0 && r < HW && c >= 0 && c < HW) ? src[r * HW + c] : 0.f;
            tile[i] = v;
            nz |= (v != 0.f);
        }
        // load 8x9 weights for this input channel
        for (int i = tid; i < OCT * 9; i += NT)
            ws[i / 9][i % 9] = wt[((size_t)(ocb + i / 9) * CIN + ic) * 9 + (i % 9)];

        if (__syncthreads_or(nz)) {
            float r[16];
#pragma unroll
            for (int dy = 0; dy < 4; ++dy)
#pragma unroll
                for (int dx = 0; dx < 4; ++dx)
                    r[dy * 4 + dx] = tile[(ty + dy) * TW + tx + dx];

#pragma unroll
            for (int o = 0; o < OCT; ++o) {
#pragma unroll
                for (int ky = 0; ky < 3; ++ky)
#pragma unroll
                    for (int kx = 0; kx < 3; ++kx) {
                        float w = ws[o][ky * 3 + kx];
                        acc[o][0] += r[ ky      * 4 + kx    ] * w;
                        acc[o][1] += r[ ky      * 4 + kx + 1] * w;
                        acc[o][2] += r[(ky + 1) * 4 + kx    ] * w;
                        acc[o][3] += r[(ky + 1) * 4 + kx + 1] * w;
                    }
            }
        }
        __syncthreads();
    }

#pragma unroll
    for (int o = 0; o < OCT; ++o) {
        float bv = bias[ocb + o];
        float* dst = out + (((size_t)b * Cout + ocb + o) * HW + ty) * HW + tx;
        dst[0]      = acc[o][0] + bv;
        dst[1]      = acc[o][1] + bv;
        dst[HW]     = acc[o][2] + bv;
        dst[HW + 1] = acc[o][3] + bv;
    }
}

// ---------------- LIF stage 1: spike + dropout mask ----------------
__global__ void lif1_kernel(const float* __restrict__ mask_f1)
{
    int i = blockIdx.x * blockDim.x + threadIdx.x;
    if (i >= B * C1_OUT * H1 * H1) return;
    float m  = g_m1[i] + g_conv1out[i];
    float sp = (m >= 1.f) ? 1.f : 0.f;
    g_m1[i] = m - sp;
    g_s1[i] = sp * mask_f1[i];
}

// ---------------- LIF stage 2 + 2x2 mean pool ----------------
__global__ void lif2pool_kernel()
{
    int idx = blockIdx.x * blockDim.x + threadIdx.x;         // [B*128, 16, 16]
    if (idx >= B * C2_OUT * H3 * H3) return;
    int x  = idx & 15;
    int y  = (idx >> 4) & 15;
    int bc = idx >> 8;
    int base = bc * (H1 * H1) + (2 * y) * H1 + 2 * x;
    float sum = 0.f;
#pragma unroll
    for (int dy = 0; dy < 2; ++dy)
#pragma unroll
        for (int dx = 0; dx < 2; ++dx) {
            int p = base + dy * H1 + dx;
            float m  = g_m2[p] + g_conv2out[p];
            float sp = (m >= 1.f) ? 1.f : 0.f;
            g_m2[p] = m - sp;
            sum += sp;
        }
    g_s2p[idx] = sum * 0.25f;
}

// ---------------- LIF stage 3 + mask_f2 + 2x2 mean pool -> [B, 8192] ----
__global__ void lif3maskpool_kernel(const float* __restrict__ mask_f2)
{
    int idx = blockIdx.x * blockDim.x + threadIdx.x;         // [B*128, 8, 8]
    if (idx >= B * C2_OUT * 8 * 8) return;
    int x  = idx & 7;
    int y  = (idx >> 3) & 7;
    int bc = idx >> 6;
    int base = bc * (H3 * H3) + (2 * y) * H3 + 2 * x;
    float sum = 0.f;
#pragma unroll
    for (int dy = 0; dy < 2; ++dy)
#pragma unroll
        for (int dx = 0; dx < 2; ++dx) {
            int p = base + dy * H3 + dx;
            float m  = g_m3[p] + g_conv3out[p];
            float sp = (m >= 1.f) ? 1.f : 0.f;
            g_m3[p] = m - sp;
            sum += sp * mask_f2[p];
        }
    g_s3p[idx] = sum * 0.25f;   // idx == b*8192 + c*64 + y*8 + x  (matches reshape)
}

// ---------------- fc1 split-K stage 1 (deterministic, no atomics) -------
// grid: (16 o-blocks of 64, 8 k-splits of 1024), block 256.
__global__ void fc1_stage1_kernel(const float* __restrict__ w)
{
    __shared__ float s_s[B][64];
    __shared__ float w_s[64][65];

    const int ob = blockIdx.x * 64;
    const int ks = blockIdx.y;
    const int k0base = ks * 1024;
    const int t  = threadIdx.x;
    const int to = t & 63;
    const int tb = (t >> 6) * 8;

    float acc[8] = {0.f,0.f,0.f,0.f,0.f,0.f,0.f,0.f};

    for (int kc = 0; kc < 1024; kc += 64) {
        const int k0 = k0base + kc;
        for (int i = t; i < B * 64; i += 256)
            s_s[i >> 6][i & 63] = g_s3p[(size_t)(i >> 6) * FC1_IN + k0 + (i & 63)];
        for (int i = t; i < 64 * 64; i += 256)
            w_s[i >> 6][i & 63] = w[(size_t)(ob + (i >> 6)) * FC1_IN + k0 + (i & 63)];
        __syncthreads();
#pragma unroll 8
        for (int kk = 0; kk < 64; ++kk) {
            float wv = w_s[to][kk];
#pragma unroll
            for (int bb = 0; bb < 8; ++bb)
                acc[bb] += s_s[tb + bb][kk] * wv;
        }
        __syncthreads();
    }
#pragma unroll
    for (int bb = 0; bb < 8; ++bb)
        g_part[(ks * B + tb + bb) * FC1_OUT + ob + to] = acc[bb];
}

// ---------------- fc1 reduce + LIF + mask_c1 ----------------
__global__ void fc1_stage2_kernel(const float* __restrict__ fc1_b,
                                  const float* __restrict__ mask_c1)
{
    int idx = blockIdx.x * blockDim.x + threadIdx.x;   // [B, 1024]
    if (idx >= B * FC1_OUT) return;
    int bo = idx;                                      // b*1024 + o
    float sum = fc1_b[idx & 1023];
#pragma unroll
    for (int ks = 0; ks < 8; ++ks)
        sum += g_part[ks * (B * FC1_OUT) + bo];
    float m  = g_c1[bo] + sum;
    float sp = (m >= 1.f) ? 1.f : 0.f;
    g_c1[bo]   = m - sp;
    g_sfc1[bo] = sp * mask_c1[bo];
}

// ---------------- fc2 + LIF (c2 lives in d_out) ----------------
__global__ void fc2_lif_kernel(const float* __restrict__ w,
                               const float* __restrict__ bias,
                               float* __restrict__ c2)
{
    int gw   = (blockIdx.x * blockDim.x + threadIdx.x) >> 5;
    int lane = threadIdx.x & 31;
    if (gw >= B * FC2_OUT) return;
    int b = gw / FC2_OUT, o = gw % FC2_OUT;
    const float* sr = g_sfc1 + (size_t)b * FC1_OUT;
    const float* wr = w + (size_t)o * FC1_OUT;
    float acc = 0.f;
    for (int k = lane; k < FC1_OUT; k += 32)
        acc += sr[k] * wr[k];
#pragma unroll
    for (int off = 16; off; off >>= 1)
        acc += __shfl_down_sync(0xFFFFFFFFu, acc, off);
    if (lane == 0) {
        float m  = c2[b * FC2_OUT + o] + acc + bias[o];
        float sp = (m >= 1.f) ? 1.f : 0.f;
        c2[b * FC2_OUT + o] = m - sp;
    }
}

// ---------------- host launcher ----------------
extern "C" void kernel_launch(void* const* d_in, const int* in_sizes, int n_in,
                              void* d_out, int out_size)
{
    const float* X       = (const float*)d_in[0];
    const float* conv1_w = (const float*)d_in[1];
    const float* conv1_b = (const float*)d_in[2];
    const float* conv2_w = (const float*)d_in[3];
    const float* conv2_b = (const float*)d_in[4];
    const float* conv3_w = (const float*)d_in[5];
    const float* conv3_b = (const float*)d_in[6];
    const float* fc1_w   = (const float*)d_in[7];
    const float* fc1_b   = (const float*)d_in[8];
    const float* fc2_w   = (const float*)d_in[9];
    const float* fc2_b   = (const float*)d_in[10];
    const float* mask_f1 = (const float*)d_in[11];
    const float* mask_f2 = (const float*)d_in[12];
    const float* mask_c1 = (const float*)d_in[13];
    // d_in[14] = timesteps (always 8 per setup_inputs)

    float* c2 = (float*)d_out;

    // zero-initialize membrane states (graph-capturable memset nodes)
    void *pm1, *pm2, *pm3, *pc1;
    cudaGetSymbolAddress(&pm1, g_m1);
    cudaGetSymbolAddress(&pm2, g_m2);
    cudaGetSymbolAddress(&pm3, g_m3);
    cudaGetSymbolAddress(&pc1, g_c1);
    cudaMemsetAsync(pm1, 0, sizeof(float) * B * C1_OUT * H1 * H1);
    cudaMemsetAsync(pm2, 0, sizeof(float) * B * C2_OUT * H1 * H1);
    cudaMemsetAsync(pm3, 0, sizeof(float) * B * C2_OUT * H3 * H3);
    cudaMemsetAsync(pc1, 0, sizeof(float) * B * FC1_OUT);
    cudaMemsetAsync(d_out, 0, sizeof(float) * B * FC2_OUT);

    float *conv1out, *s1, *conv2out, *s2p, *conv3out;
    cudaGetSymbolAddress((void**)&conv1out, g_conv1out);
    cudaGetSymbolAddress((void**)&s1,       g_s1);
    cudaGetSymbolAddress((void**)&conv2out, g_conv2out);
    cudaGetSymbolAddress((void**)&s2p,      g_s2p);
    cudaGetSymbolAddress((void**)&conv3out, g_conv3out);

    // conv1 depends only on X -> compute once
    conv3x3_kernel<C1_IN, H1><<<dim3(C1_OUT / 8, B), 256>>>(X, conv1_w, conv1_b, conv1out, C1_OUT);

    const int n1 = B * C1_OUT * H1 * H1;              // 2,097,152
    const int n2p = B * C2_OUT * H3 * H3;             // 1,048,576
    const int n3p = B * C2_OUT * 8 * 8;               //   262,144

    for (int t = 0; t < TSTEPS; ++t) {
        lif1_kernel<<<(n1 + 255) / 256, 256>>>(mask_f1);

        conv3x3_kernel<C1_OUT, H1><<<dim3(C2_OUT / 8, B), 256>>>(s1, conv2_w, conv2_b, conv2out, C2_OUT);

        lif2pool_kernel<<<(n2p + 255) / 256, 256>>>();

        conv3x3_kernel<C2_OUT, H3><<<dim3(C2_OUT / 8, B), 64>>>(s2p, conv3_w, conv3_b, conv3out, C2_OUT);

        lif3maskpool_kernel<<<(n3p + 255) / 256, 256>>>(mask_f2);

        fc1_stage1_kernel<<<dim3(FC1_OUT / 64, 8), 256>>>(fc1_w);
        fc1_stage2_kernel<<<(B * FC1_OUT + 255) / 256, 256>>>(fc1_b, mask_c1);

        fc2_lif_kernel<<<(B * FC2_OUT * 32 + 127) / 128, 128>>>(fc2_w, fc2_b, c2);
    }
}

// round 2
// speedup vs baseline: 2.5020x; 2.5020x over previous
#include <cuda_runtime.h>
#include <cstdint>

typedef unsigned long long u64;

// ---------------- problem constants ----------------
#define B       32
#define TSTEPS  8
#define C1_OUT  64
#define H1      32
#define C2_OUT  128
#define H3      16
#define FC1_IN  8192
#define FC1_OUT 1024
#define FC2_OUT 10

#define N1 (B * C1_OUT * H1 * H1)   // 2,097,152

// ---------------- device state / scratch ----------------
__device__ float g_conv1out[N1];                      // 8 MB
__device__ float g_s1t     [TSTEPS * N1];             // 64 MB : precomputed layer-1 spikes, all timesteps
__device__ float g_conv2out[B * C2_OUT * H1 * H1];    // 16 MB
__device__ float g_m2      [B * C2_OUT * H1 * H1];    // 16 MB
__device__ float g_s2p     [B * C2_OUT * H3 * H3];    // 4 MB
__device__ float g_conv3out[B * C2_OUT * H3 * H3];    // 4 MB
__device__ float g_m3      [B * C2_OUT * H3 * H3];    // 4 MB
__device__ float g_s3p     [B * FC1_IN];              // 1 MB
__device__ float g_part    [8 * B * FC1_OUT];         // 1 MB
__device__ float g_c1      [B * FC1_OUT];
__device__ float g_sfc1    [B * FC1_OUT];

// ---------------- f32x2 packed helpers ----------------
__device__ __forceinline__ u64 pack2(float lo, float hi) {
    u64 r;
    asm("mov.b64 %0, {%1, %2};" : "=l"(r) : "f"(lo), "f"(hi));
    return r;
}
__device__ __forceinline__ void ffma2(u64& acc, u64 a, u64 b) {
    asm("fma.rn.f32x2 %0, %1, %2, %0;" : "+l"(acc) : "l"(a), "l"(b));
}
__device__ __forceinline__ u64 add2(u64 a, u64 b) {
    u64 r;
    asm("add.rn.f32x2 %0, %1, %2;" : "=l"(r) : "l"(a), "l"(b));
    return r;
}
__device__ __forceinline__ void cp_async4(uint32_t saddr, const void* gaddr, int srcsize) {
    asm volatile("cp.async.ca.shared.global [%0], [%1], 4, %2;"
                 :: "r"(saddr), "l"(gaddr), "r"(srcsize));
}
__device__ __forceinline__ void cp_commit() { asm volatile("cp.async.commit_group;"); }
__device__ __forceinline__ void cp_wait0()  { asm volatile("cp.async.wait_group 0;"); }

// ======================================================================
// Pipelined 3x3 SAME conv, f32x2 packed math.
//  - GB batches per block (each handled by a TSUB=(HW/2)^2 thread subgroup)
//  - OCT=8 output channels per block
//  - ICB input channels staged per barrier, cp.async double-buffered
//  - weights stored in smem as pre-duplicated {w,w} u64 pairs
// ======================================================================
template<int CIN, int HW, int GB, int ICB>
__global__ void __launch_bounds__(GB*(HW/2)*(HW/2))
conv3x3_pipe(const float* __restrict__ in,
             const float* __restrict__ wt,
             const float* __restrict__ bias,
             float* __restrict__ out,
             int Cout)
{
    constexpr int TP    = HW / 2;
    constexpr int TSUB  = TP * TP;
    constexpr int NT    = GB * TSUB;
    constexpr int TW    = HW + 2;
    constexpr int TS    = TW * TW;
    constexpr int OCT   = 8;
    constexpr int NST   = CIN / ICB;
    constexpr int LSLOT = (TS + TSUB - 1) / TSUB;
    constexpr int WTOT  = ICB * OCT * 9;
    constexpr int WSLOT = (WTOT + NT - 1) / NT;

    __shared__ float tile[2][ICB][GB][TS];
    __shared__ u64   ws  [2][ICB][OCT * 9];

    const int tid = threadIdx.x;
    const int sub = tid / TSUB;
    const int st  = tid % TSUB;
    const int b   = blockIdx.y * GB + sub;
    const int ocb = blockIdx.x * OCT;
    const int ty  = (st / TP) * 2;
    const int tx  = (st % TP) * 2;

    const float* inb = in + (size_t)b * CIN * HW * HW;

    // ---- precompute tile-load slots (index math hoisted out of channel loop)
    int  l_soff[LSLOT];   // smem float offset within one channel tile (-1 = dead)
    int  l_goff[LSLOT];   // gmem float offset within one channel image
    int  l_size[LSLOT];   // 4 = real load, 0 = zero-fill (halo)
#pragma unroll
    for (int k = 0; k < LSLOT; ++k) {
        int i = st + k * TSUB;
        int r = i / TW - 1, c = i % TW - 1;
        bool live = (i < TS);
        bool inb_ = live && r >= 0 && r < HW && c >= 0 && c < HW;
        l_soff[k] = live ? i : -1;
        l_goff[k] = inb_ ? (r * HW + c) : 0;
        l_size[k] = inb_ ? 4 : 0;
    }

    float wreg[WSLOT];

    auto issue_loads = [&](int s, int buf) {
#pragma unroll
        for (int ic = 0; ic < ICB; ++ic) {
            const float* src = inb + (size_t)(s * ICB + ic) * HW * HW;
#pragma unroll
            for (int k = 0; k < LSLOT; ++k) {
                if (l_soff[k] >= 0) {
                    uint32_t d = (uint32_t)__cvta_generic_to_shared(&tile[buf][ic][sub][l_soff[k]]);
                    cp_async4(d, src + l_goff[k], l_size[k]);
                }
            }
        }
    };
    auto load_w = [&](int s) {
#pragma unroll
        for (int j = 0; j < WSLOT; ++j) {
            int i = tid + j * NT;
            if (i < WTOT) {
                int ic = i / (OCT * 9), rem = i % (OCT * 9);
                int o = rem / 9, k = rem % 9;
                wreg[j] = wt[((size_t)(ocb + o) * CIN + s * ICB + ic) * 9 + k];
            }
        }
    };
    auto store_w = [&](int buf) {
#pragma unroll
        for (int j = 0; j < WSLOT; ++j) {
            int i = tid + j * NT;
            if (i < WTOT) {
                int ic = i / (OCT * 9), rem = i % (OCT * 9);
                ws[buf][ic][rem] = pack2(wreg[j], wreg[j]);
            }
        }
    };

    // packed accumulators: [oc][row 0/1], each holds pixels (tx, tx+1)
    u64 pa[OCT][2];
#pragma unroll
    for (int o = 0; o < OCT; ++o) { pa[o][0] = 0ull; pa[o][1] = 0ull; }

    auto compute = [&](int buf) {
#pragma unroll
        for (int ic = 0; ic < ICB; ++ic) {
            const float* tp = &tile[buf][ic][sub][0];
            float r[4][4];
            unsigned nz = 0u;
#pragma unroll
            for (int dy = 0; dy < 4; ++dy)
#pragma unroll
                for (int dx = 0; dx < 4; ++dx) {
                    float v = tp[(ty + dy) * TW + tx + dx];
                    r[dy][dx] = v;
                    nz |= __float_as_uint(v);
                }
            if (__any_sync(0xffffffffu, nz != 0u)) {
                u64 pr[4][3];
#pragma unroll
                for (int dy = 0; dy < 4; ++dy)
#pragma unroll
                    for (int kx = 0; kx < 3; ++kx)
                        pr[dy][kx] = pack2(r[dy][kx], r[dy][kx + 1]);
#pragma unroll
                for (int o = 0; o < OCT; ++o) {
                    const u64* w9 = &ws[buf][ic][o * 9];
#pragma unroll
                    for (int ky = 0; ky < 3; ++ky) {
                        u64 w0 = w9[ky * 3 + 0], w1 = w9[ky * 3 + 1], w2 = w9[ky * 3 + 2];
                        ffma2(pa[o][0], pr[ky    ][0], w0);
                        ffma2(pa[o][0], pr[ky    ][1], w1);
                        ffma2(pa[o][0], pr[ky    ][2], w2);
                        ffma2(pa[o][1], pr[ky + 1][0], w0);
                        ffma2(pa[o][1], pr[ky + 1][1], w1);
                        ffma2(pa[o][1], pr[ky + 1][2], w2);
                    }
                }
            }
        }
    };

    // ---- prologue: stage 0
    load_w(0); store_w(0);
    issue_loads(0, 0);
    cp_commit();
    cp_wait0();
    __syncthreads();

    // ---- pipelined main loop
#pragma unroll 2
    for (int s = 0; s < NST; ++s) {
        int buf = s & 1;
        if (s + 1 < NST) {
            issue_loads(s + 1, buf ^ 1);
            cp_commit();
            load_w(s + 1);
        }
        compute(buf);
        if (s + 1 < NST) {
            cp_wait0();
            store_w(buf ^ 1);
        }
        __syncthreads();
    }

    // ---- epilogue
#pragma unroll
    for (int o = 0; o < OCT; ++o) {
        float bv = bias[ocb + o];
        u64 bp = pack2(bv, bv);
        u64 r0 = add2(pa[o][0], bp);
        u64 r1 = add2(pa[o][1], bp);
        float* dst = out + (((size_t)b * Cout + ocb + o) * HW + ty) * HW + tx;
        *(u64*)(dst)      = r0;
        *(u64*)(dst + HW) = r1;
    }
}

// ---------------- layer-1 LIF for ALL timesteps (input static) --------
__global__ void lif1_all_kernel(const float* __restrict__ mask_f1)
{
    int i = blockIdx.x * blockDim.x + threadIdx.x;
    if (i >= N1) return;
    float x = g_conv1out[i];
    float mk = mask_f1[i];
    float m = 0.f;
#pragma unroll
    for (int t = 0; t < TSTEPS; ++t) {
        m += x;
        float sp = (m >= 1.f) ? 1.f : 0.f;
        m -= sp;
        g_s1t[(size_t)t * N1 + i] = sp * mk;
    }
}

// ---------------- LIF stage 2 + 2x2 mean pool ----------------
__global__ void lif2pool_kernel()
{
    int idx = blockIdx.x * blockDim.x + threadIdx.x;         // [B*128, 16, 16]
    if (idx >= B * C2_OUT * H3 * H3) return;
    int x  = idx & 15;
    int y  = (idx >> 4) & 15;
    int bc = idx >> 8;
    int base = bc * (H1 * H1) + (2 * y) * H1 + 2 * x;
    float sum = 0.f;
#pragma unroll
    for (int dy = 0; dy < 2; ++dy)
#pragma unroll
        for (int dx = 0; dx < 2; ++dx) {
            int p = base + dy * H1 + dx;
            float m  = g_m2[p] + g_conv2out[p];
            float sp = (m >= 1.f) ? 1.f : 0.f;
            g_m2[p] = m - sp;
            sum += sp;
        }
    g_s2p[idx] = sum * 0.25f;
}

// ---------------- LIF stage 3 + mask_f2 + 2x2 mean pool ----------------
__global__ void lif3maskpool_kernel(const float* __restrict__ mask_f2)
{
    int idx = blockIdx.x * blockDim.x + threadIdx.x;         // [B*128, 8, 8]
    if (idx >= B * C2_OUT * 8 * 8) return;
    int x  = idx & 7;
    int y  = (idx >> 3) & 7;
    int bc = idx >> 6;
    int base = bc * (H3 * H3) + (2 * y) * H3 + 2 * x;
    float sum = 0.f;
#pragma unroll
    for (int dy = 0; dy < 2; ++dy)
#pragma unroll
        for (int dx = 0; dx < 2; ++dx) {
            int p = base + dy * H3 + dx;
            float m  = g_m3[p] + g_conv3out[p];
            float sp = (m >= 1.f) ? 1.f : 0.f;
            g_m3[p] = m - sp;
            sum += sp * mask_f2[p];
        }
    g_s3p[idx] = sum * 0.25f;
}

// ---------------- fc1 split-K stage 1 ----------------
__global__ void fc1_stage1_kernel(const float* __restrict__ w)
{
    __shared__ float s_s[B][64];
    __shared__ float w_s[64][65];

    const int ob = blockIdx.x * 64;
    const int ks = blockIdx.y;
    const int k0base = ks * 1024;
    const int t  = threadIdx.x;
    const int to = t & 63;
    const int tb = (t >> 6) * 8;

    float acc[8] = {0.f,0.f,0.f,0.f,0.f,0.f,0.f,0.f};

    for (int kc = 0; kc < 1024; kc += 64) {
        const int k0 = k0base + kc;
        for (int i = t; i < B * 64; i += 256)
            s_s[i >> 6][i & 63] = g_s3p[(size_t)(i >> 6) * FC1_IN + k0 + (i & 63)];
        for (int i = t; i < 64 * 64; i += 256)
            w_s[i >> 6][i & 63] = w[(size_t)(ob + (i >> 6)) * FC1_IN + k0 + (i & 63)];
        __syncthreads();
#pragma unroll 8
        for (int kk = 0; kk < 64; ++kk) {
            float wv = w_s[to][kk];
#pragma unroll
            for (int bb = 0; bb < 8; ++bb)
                acc[bb] += s_s[tb + bb][kk] * wv;
        }
        __syncthreads();
    }
#pragma unroll
    for (int bb = 0; bb < 8; ++bb)
        g_part[(ks * B + tb + bb) * FC1_OUT + ob + to] = acc[bb];
}

// ---------------- fc1 reduce + LIF + mask_c1 ----------------
__global__ void fc1_stage2_kernel(const float* __restrict__ fc1_b,
                                  const float* __restrict__ mask_c1)
{
    int idx = blockIdx.x * blockDim.x + threadIdx.x;   // [B, 1024]
    if (idx >= B * FC1_OUT) return;
    float sum = fc1_b[idx & 1023];
#pragma unroll
    for (int ks = 0; ks < 8; ++ks)
        sum += g_part[ks * (B * FC1_OUT) + idx];
    float m  = g_c1[idx] + sum;
    float sp = (m >= 1.f) ? 1.f : 0.f;
    g_c1[idx]   = m - sp;
    g_sfc1[idx] = sp * mask_c1[idx];
}

// ---------------- fc2 + LIF (c2 lives in d_out) ----------------
__global__ void fc2_lif_kernel(const float* __restrict__ w,
                               const float* __restrict__ bias,
                               float* __restrict__ c2)
{
    int gw   = (blockIdx.x * blockDim.x + threadIdx.x) >> 5;
    int lane = threadIdx.x & 31;
    if (gw >= B * FC2_OUT) return;
    int b = gw / FC2_OUT, o = gw % FC2_OUT;
    const float* sr = g_sfc1 + (size_t)b * FC1_OUT;
    const float* wr = w + (size_t)o * FC1_OUT;
    float acc = 0.f;
    for (int k = lane; k < FC1_OUT; k += 32)
        acc += sr[k] * wr[k];
#pragma unroll
    for (int off = 16; off; off >>= 1)
        acc += __shfl_down_sync(0xFFFFFFFFu, acc, off);
    if (lane == 0) {
        float m  = c2[b * FC2_OUT + o] + acc + bias[o];
        float sp = (m >= 1.f) ? 1.f : 0.f;
        c2[b * FC2_OUT + o] = m - sp;
    }
}

// ---------------- host launcher ----------------
extern "C" void kernel_launch(void* const* d_in, const int* in_sizes, int n_in,
                              void* d_out, int out_size)
{
    const float* X       = (const float*)d_in[0];
    const float* conv1_w = (const float*)d_in[1];
    const float* conv1_b = (const float*)d_in[2];
    const float* conv2_w = (const float*)d_in[3];
    const float* conv2_b = (const float*)d_in[4];
    const float* conv3_w = (const float*)d_in[5];
    const float* conv3_b = (const float*)d_in[6];
    const float* fc1_w   = (const float*)d_in[7];
    const float* fc1_b   = (const float*)d_in[8];
    const float* fc2_w   = (const float*)d_in[9];
    const float* fc2_b   = (const float*)d_in[10];
    const float* mask_f1 = (const float*)d_in[11];
    const float* mask_f2 = (const float*)d_in[12];
    const float* mask_c1 = (const float*)d_in[13];

    float* c2 = (float*)d_out;

    void *pm2, *pm3, *pc1;
    cudaGetSymbolAddress(&pm2, g_m2);
    cudaGetSymbolAddress(&pm3, g_m3);
    cudaGetSymbolAddress(&pc1, g_c1);
    cudaMemsetAsync(pm2, 0, sizeof(float) * B * C2_OUT * H1 * H1);
    cudaMemsetAsync(pm3, 0, sizeof(float) * B * C2_OUT * H3 * H3);
    cudaMemsetAsync(pc1, 0, sizeof(float) * B * FC1_OUT);
    cudaMemsetAsync(d_out, 0, sizeof(float) * B * FC2_OUT);

    float *conv1out, *s1t, *conv2out, *s2p, *conv3out;
    cudaGetSymbolAddress((void**)&conv1out, g_conv1out);
    cudaGetSymbolAddress((void**)&s1t,      g_s1t);
    cudaGetSymbolAddress((void**)&conv2out, g_conv2out);
    cudaGetSymbolAddress((void**)&s2p,      g_s2p);
    cudaGetSymbolAddress((void**)&conv3out, g_conv3out);

    // layer 1 hoisted: conv1 once, then LIF over all 8 timesteps once
    conv3x3_pipe<3, H1, 1, 1><<<dim3(C1_OUT / 8, B), 256>>>(X, conv1_w, conv1_b, conv1out, C1_OUT);
    lif1_all_kernel<<<(N1 + 255) / 256, 256>>>(mask_f1);

    const int n2p = B * C2_OUT * H3 * H3;
    const int n3p = B * C2_OUT * 8 * 8;

    for (int t = 0; t < TSTEPS; ++t) {
        conv3x3_pipe<C1_OUT, H1, 1, 4><<<dim3(C2_OUT / 8, B), 256>>>(
            s1t + (size_t)t * N1, conv2_w, conv2_b, conv2out, C2_OUT);

        lif2pool_kernel<<<(n2p + 255) / 256, 256>>>();

        conv3x3_pipe<C2_OUT, H3, 2, 4><<<dim3(C2_OUT / 8, B / 2), 128>>>(
            s2p, conv3_w, conv3_b, conv3out, C2_OUT);

        lif3maskpool_kernel<<<(n3p + 255) / 256, 256>>>(mask_f2);

        fc1_stage1_kernel<<<dim3(FC1_OUT / 64, 8), 256>>>(fc1_w);
        fc1_stage2_kernel<<<(B * FC1_OUT + 255) / 256, 256>>>(fc1_b, mask_c1);

        fc2_lif_kernel<<<(B * FC2_OUT * 32 + 127) / 128, 128>>>(fc2_w, fc2_b, c2);
    }
}

// round 3
// speedup vs baseline: 4.2570x; 1.7014x over previous
#include <cuda_runtime.h>
#include <cstdint>

typedef unsigned long long u64;

// ---------------- problem constants ----------------
#define B       32
#define TSTEPS  8
#define C1_OUT  64
#define H1      32
#define C2_OUT  128
#define H3      16
#define FC1_IN  8192
#define FC1_OUT 1024
#define FC2_OUT 10
#define ROWS    (TSTEPS * B)        // 256 "virtual batches" (t*32+b)
#define KSPLIT  4

#define N1 (B * C1_OUT * H1 * H1)   // 2,097,152

// ---------------- device scratch ----------------
__device__ float g_conv1out    [N1];                            //   8 MB
__device__ float g_s1t         [ROWS * C1_OUT * H1 * H1];       //  64 MB
__device__ float g_conv2out_all[ROWS * C2_OUT * H1 * H1];       // 128 MB
__device__ float g_s2p_all     [ROWS * C2_OUT * H3 * H3];       //  32 MB
__device__ float g_conv3out_all[ROWS * C2_OUT * H3 * H3];       //  32 MB
__device__ float g_s3p_all     [ROWS * FC1_IN];                 //   8 MB
__device__ float g_part        [KSPLIT * ROWS * FC1_OUT];       //   4 MB
__device__ float g_sfc1_all    [ROWS * FC1_OUT];                //   1 MB
__device__ float g_fc2out      [ROWS * FC2_OUT];

// ---------------- f32x2 packed helpers ----------------
__device__ __forceinline__ u64 pack2(float lo, float hi) {
    u64 r;
    asm("mov.b64 %0, {%1, %2};" : "=l"(r) : "f"(lo), "f"(hi));
    return r;
}
__device__ __forceinline__ void ffma2(u64& acc, u64 a, u64 b) {
    asm("fma.rn.f32x2 %0, %1, %2, %0;" : "+l"(acc) : "l"(a), "l"(b));
}
__device__ __forceinline__ u64 add2(u64 a, u64 b) {
    u64 r;
    asm("add.rn.f32x2 %0, %1, %2;" : "=l"(r) : "l"(a), "l"(b));
    return r;
}
__device__ __forceinline__ void cp_async4(uint32_t saddr, const void* gaddr, int srcsize) {
    asm volatile("cp.async.ca.shared.global [%0], [%1], 4, %2;"
                 :: "r"(saddr), "l"(gaddr), "r"(srcsize));
}
__device__ __forceinline__ void cp_commit() { asm volatile("cp.async.commit_group;"); }
__device__ __forceinline__ void cp_wait0()  { asm volatile("cp.async.wait_group 0;"); }

// ======================================================================
// Pipelined 3x3 SAME conv, f32x2 packed math (unchanged from R2, but now
// launched with the 8 timesteps folded into the batch grid dimension).
// ======================================================================
template<int CIN, int HW, int GB, int ICB>
__global__ void __launch_bounds__(GB*(HW/2)*(HW/2))
conv3x3_pipe(const float* __restrict__ in,
             const float* __restrict__ wt,
             const float* __restrict__ bias,
             float* __restrict__ out,
             int Cout)
{
    constexpr int TP    = HW / 2;
    constexpr int TSUB  = TP * TP;
    constexpr int NT    = GB * TSUB;
    constexpr int TW    = HW + 2;
    constexpr int TS    = TW * TW;
    constexpr int OCT   = 8;
    constexpr int NST   = CIN / ICB;
    constexpr int LSLOT = (TS + TSUB - 1) / TSUB;
    constexpr int WTOT  = ICB * OCT * 9;
    constexpr int WSLOT = (WTOT + NT - 1) / NT;

    __shared__ float tile[2][ICB][GB][TS];
    __shared__ u64   ws  [2][ICB][OCT * 9];

    const int tid = threadIdx.x;
    const int sub = tid / TSUB;
    const int st  = tid % TSUB;
    const int b   = blockIdx.y * GB + sub;
    const int ocb = blockIdx.x * OCT;
    const int ty  = (st / TP) * 2;
    const int tx  = (st % TP) * 2;

    const float* inb = in + (size_t)b * CIN * HW * HW;

    int  l_soff[LSLOT];
    int  l_goff[LSLOT];
    int  l_size[LSLOT];
#pragma unroll
    for (int k = 0; k < LSLOT; ++k) {
        int i = st + k * TSUB;
        int r = i / TW - 1, c = i % TW - 1;
        bool live = (i < TS);
        bool inb_ = live && r >= 0 && r < HW && c >= 0 && c < HW;
        l_soff[k] = live ? i : -1;
        l_goff[k] = inb_ ? (r * HW + c) : 0;
        l_size[k] = inb_ ? 4 : 0;
    }

    float wreg[WSLOT];

    auto issue_loads = [&](int s, int buf) {
#pragma unroll
        for (int ic = 0; ic < ICB; ++ic) {
            const float* src = inb + (size_t)(s * ICB + ic) * HW * HW;
#pragma unroll
            for (int k = 0; k < LSLOT; ++k) {
                if (l_soff[k] >= 0) {
                    uint32_t d = (uint32_t)__cvta_generic_to_shared(&tile[buf][ic][sub][l_soff[k]]);
                    cp_async4(d, src + l_goff[k], l_size[k]);
                }
            }
        }
    };
    auto load_w = [&](int s) {
#pragma unroll
        for (int j = 0; j < WSLOT; ++j) {
            int i = tid + j * NT;
            if (i < WTOT) {
                int ic = i / (OCT * 9), rem = i % (OCT * 9);
                int o = rem / 9, k = rem % 9;
                wreg[j] = wt[((size_t)(ocb + o) * CIN + s * ICB + ic) * 9 + k];
            }
        }
    };
    auto store_w = [&](int buf) {
#pragma unroll
        for (int j = 0; j < WSLOT; ++j) {
            int i = tid + j * NT;
            if (i < WTOT) {
                int ic = i / (OCT * 9), rem = i % (OCT * 9);
                ws[buf][ic][rem] = pack2(wreg[j], wreg[j]);
            }
        }
    };

    u64 pa[OCT][2];
#pragma unroll
    for (int o = 0; o < OCT; ++o) { pa[o][0] = 0ull; pa[o][1] = 0ull; }

    auto compute = [&](int buf) {
#pragma unroll
        for (int ic = 0; ic < ICB; ++ic) {
            const float* tp = &tile[buf][ic][sub][0];
            float r[4][4];
            unsigned nz = 0u;
#pragma unroll
            for (int dy = 0; dy < 4; ++dy)
#pragma unroll
                for (int dx = 0; dx < 4; ++dx) {
                    float v = tp[(ty + dy) * TW + tx + dx];
                    r[dy][dx] = v;
                    nz |= __float_as_uint(v);
                }
            if (__any_sync(0xffffffffu, nz != 0u)) {
                u64 pr[4][3];
#pragma unroll
                for (int dy = 0; dy < 4; ++dy)
#pragma unroll
                    for (int kx = 0; kx < 3; ++kx)
                        pr[dy][kx] = pack2(r[dy][kx], r[dy][kx + 1]);
#pragma unroll
                for (int o = 0; o < OCT; ++o) {
                    const u64* w9 = &ws[buf][ic][o * 9];
#pragma unroll
                    for (int ky = 0; ky < 3; ++ky) {
                        u64 w0 = w9[ky * 3 + 0], w1 = w9[ky * 3 + 1], w2 = w9[ky * 3 + 2];
                        ffma2(pa[o][0], pr[ky    ][0], w0);
                        ffma2(pa[o][0], pr[ky    ][1], w1);
                        ffma2(pa[o][0], pr[ky    ][2], w2);
                        ffma2(pa[o][1], pr[ky + 1][0], w0);
                        ffma2(pa[o][1], pr[ky + 1][1], w1);
                        ffma2(pa[o][1], pr[ky + 1][2], w2);
                    }
                }
            }
        }
    };

    load_w(0); store_w(0);
    issue_loads(0, 0);
    cp_commit();
    cp_wait0();
    __syncthreads();

#pragma unroll 2
    for (int s = 0; s < NST; ++s) {
        int buf = s & 1;
        if (s + 1 < NST) {
            issue_loads(s + 1, buf ^ 1);
            cp_commit();
            load_w(s + 1);
        }
        compute(buf);
        if (s + 1 < NST) {
            cp_wait0();
            store_w(buf ^ 1);
        }
        __syncthreads();
    }

#pragma unroll
    for (int o = 0; o < OCT; ++o) {
        float bv = bias[ocb + o];
        u64 bp = pack2(bv, bv);
        u64 r0 = add2(pa[o][0], bp);
        u64 r1 = add2(pa[o][1], bp);
        float* dst = out + (((size_t)b * Cout + ocb + o) * HW + ty) * HW + tx;
        *(u64*)(dst)      = r0;
        *(u64*)(dst + HW) = r1;
    }
}

// ---------------- layer-1 LIF for ALL timesteps ----------------
__global__ void lif1_all_kernel(const float* __restrict__ mask_f1)
{
    int i = blockIdx.x * blockDim.x + threadIdx.x;
    if (i >= N1) return;
    float x = g_conv1out[i];
    float mk = mask_f1[i];
    float m = 0.f;
#pragma unroll
    for (int t = 0; t < TSTEPS; ++t) {
        m += x;
        float sp = (m >= 1.f) ? 1.f : 0.f;
        m -= sp;
        g_s1t[(size_t)t * N1 + i] = sp * mk;
    }
}

// ---------------- LIF-2 + pool, ALL timesteps (m2 in registers) --------
__global__ void lif2pool_all_kernel()
{
    int idx = blockIdx.x * blockDim.x + threadIdx.x;   // [B,128,16,16]
    if (idx >= B * C2_OUT * H3 * H3) return;
    int px = idx & 15;
    int py = (idx >> 4) & 15;
    int c  = (idx >> 8) & 127;
    int b  = idx >> 15;
    const size_t chanstride = (size_t)B * C2_OUT * H1 * H1;   // per-t slab
    size_t base = ((size_t)b * C2_OUT + c) * (H1 * H1) + (2 * py) * H1 + 2 * px;
    size_t obase = ((size_t)b * C2_OUT + c) * (H3 * H3) + py * H3 + px;
    float m0 = 0.f, m1 = 0.f, m2v = 0.f, m3v = 0.f;
#pragma unroll
    for (int t = 0; t < TSTEPS; ++t) {
        float2 a = *(const float2*)&g_conv2out_all[base + (size_t)t * chanstride];
        float2 bq = *(const float2*)&g_conv2out_all[base + H1 + (size_t)t * chanstride];
        m0 += a.x;  float s0 = (m0 >= 1.f) ? 1.f : 0.f;  m0 -= s0;
        m1 += a.y;  float s1 = (m1 >= 1.f) ? 1.f : 0.f;  m1 -= s1;
        m2v += bq.x; float s2 = (m2v >= 1.f) ? 1.f : 0.f; m2v -= s2;
        m3v += bq.y; float s3 = (m3v >= 1.f) ? 1.f : 0.f; m3v -= s3;
        g_s2p_all[obase + (size_t)t * (B * C2_OUT * H3 * H3)] = (s0 + s1 + s2 + s3) * 0.25f;
    }
}

// ---------------- LIF-3 + mask_f2 + pool, ALL timesteps ----------------
__global__ void lif3maskpool_all_kernel(const float* __restrict__ mask_f2)
{
    int idx = blockIdx.x * blockDim.x + threadIdx.x;   // [B,128,8,8]
    if (idx >= B * C2_OUT * 8 * 8) return;
    int px = idx & 7;
    int py = (idx >> 3) & 7;
    int c  = (idx >> 6) & 127;
    int b  = idx >> 13;
    const size_t slab = (size_t)B * C2_OUT * H3 * H3;
    size_t base = ((size_t)b * C2_OUT + c) * (H3 * H3) + (2 * py) * H3 + 2 * px;
    size_t obase = ((size_t)b * C2_OUT + c) * 64 + py * 8 + px;
    float2 mka = *(const float2*)&mask_f2[base];
    float2 mkb = *(const float2*)&mask_f2[base + H3];
    float m0 = 0.f, m1 = 0.f, m2v = 0.f, m3v = 0.f;
#pragma unroll
    for (int t = 0; t < TSTEPS; ++t) {
        float2 a = *(const float2*)&g_conv3out_all[base + (size_t)t * slab];
        float2 bq = *(const float2*)&g_conv3out_all[base + H3 + (size_t)t * slab];
        m0 += a.x;  float s0 = (m0 >= 1.f) ? 1.f : 0.f;  m0 -= s0;
        m1 += a.y;  float s1 = (m1 >= 1.f) ? 1.f : 0.f;  m1 -= s1;
        m2v += bq.x; float s2 = (m2v >= 1.f) ? 1.f : 0.f; m2v -= s2;
        m3v += bq.y; float s3 = (m3v >= 1.f) ? 1.f : 0.f; m3v -= s3;
        g_s3p_all[obase + (size_t)t * (B * FC1_IN)] =
            (s0 * mka.x + s1 * mka.y + s2 * mkb.x + s3 * mkb.y) * 0.25f;
    }
}

// ---------------- fc1 GEMM, all timesteps: [256,8192]x[8192,1024] -------
// block: 256 thr, tile 64 out x 64 batch, k-split 4 (2048 each), f32x2.
__global__ void __launch_bounds__(256)
fc1_gemm_kernel(const float* __restrict__ w)
{
    __shared__ float w_s [64][68];     // [kk][out]
    __shared__ u64   sp_s[64][34];     // [kk][batch pair]

    const int ob = blockIdx.x * 64;
    const int bt = blockIdx.y * 64;
    const int ks = blockIdx.z;
    const int t  = threadIdx.x;
    const int to = t & 15;             // 4 outs: 4*to..4*to+3
    const int tp = t >> 4;             // 2 pairs: 2*tp, 2*tp+1 (batches 4tp..4tp+3)
    const int kk0  = t & 63;
    const int lrow = t >> 6;           // 0..3

    u64 acc[4][2];
#pragma unroll
    for (int i = 0; i < 4; ++i) { acc[i][0] = 0ull; acc[i][1] = 0ull; }

    for (int kc = 0; kc < 2048; kc += 64) {
        const int k0 = ks * 2048 + kc;
#pragma unroll
        for (int j = 0; j < 16; ++j)
            w_s[kk0][lrow + j * 4] = w[(size_t)(ob + lrow + j * 4) * FC1_IN + k0 + kk0];
#pragma unroll
        for (int j = 0; j < 8; ++j) {
            int p = lrow + j * 4;
            float lo = g_s3p_all[(size_t)(bt + 2 * p    ) * FC1_IN + k0 + kk0];
            float hi = g_s3p_all[(size_t)(bt + 2 * p + 1) * FC1_IN + k0 + kk0];
            sp_s[kk0][p] = pack2(lo, hi);
        }
        __syncthreads();
#pragma unroll
        for (int kk = 0; kk < 64; ++kk) {
            float4 wv = *(const float4*)&w_s[kk][4 * to];
            u64 w0 = pack2(wv.x, wv.x), w1 = pack2(wv.y, wv.y);
            u64 w2 = pack2(wv.z, wv.z), w3 = pack2(wv.w, wv.w);
            u64 s0 = sp_s[kk][2 * tp], s1 = sp_s[kk][2 * tp + 1];
            ffma2(acc[0][0], s0, w0); ffma2(acc[0][1], s1, w0);
            ffma2(acc[1][0], s0, w1); ffma2(acc[1][1], s1, w1);
            ffma2(acc[2][0], s0, w2); ffma2(acc[2][1], s1, w2);
            ffma2(acc[3][0], s0, w3); ffma2(acc[3][1], s1, w3);
        }
        __syncthreads();
    }
#pragma unroll
    for (int i = 0; i < 4; ++i) {
        float x0, x1, x2, x3;
        asm("mov.b64 {%0, %1}, %2;" : "=f"(x0), "=f"(x1) : "l"(acc[i][0]));
        asm("mov.b64 {%0, %1}, %2;" : "=f"(x2), "=f"(x3) : "l"(acc[i][1]));
        size_t o = ob + 4 * to + i;
        g_part[((size_t)ks * ROWS + bt + 4 * tp + 0) * FC1_OUT + o] = x0;
        g_part[((size_t)ks * ROWS + bt + 4 * tp + 1) * FC1_OUT + o] = x1;
        g_part[((size_t)ks * ROWS + bt + 4 * tp + 2) * FC1_OUT + o] = x2;
        g_part[((size_t)ks * ROWS + bt + 4 * tp + 3) * FC1_OUT + o] = x3;
    }
}

// ---------------- fc1 reduce + LIF chain + mask_c1, all timesteps -------
__global__ void fc1_chain_kernel(const float* __restrict__ fc1_b,
                                 const float* __restrict__ mask_c1)
{
    int idx = blockIdx.x * blockDim.x + threadIdx.x;   // [B, 1024]
    if (idx >= B * FC1_OUT) return;
    int b = idx >> 10, o = idx & 1023;
    float mk = mask_c1[idx];
    float bias = fc1_b[o];
    float m = 0.f;
#pragma unroll
    for (int t = 0; t < TSTEPS; ++t) {
        int row = t * B + b;
        float sum = bias;
#pragma unroll
        for (int ks = 0; ks < KSPLIT; ++ks)
            sum += g_part[((size_t)ks * ROWS + row) * FC1_OUT + o];
        m += sum;
        float sp = (m >= 1.f) ? 1.f : 0.f;
        m -= sp;
        g_sfc1_all[(size_t)row * FC1_OUT + o] = sp * mk;
    }
}

// ---------------- fc2 batched: warp per (row, out) ----------------
__global__ void fc2_all_kernel(const float* __restrict__ w)
{
    int gw   = (blockIdx.x * blockDim.x + threadIdx.x) >> 5;
    int lane = threadIdx.x & 31;
    if (gw >= ROWS * FC2_OUT) return;
    int row = gw / FC2_OUT, o = gw % FC2_OUT;
    const float* sr = g_sfc1_all + (size_t)row * FC1_OUT;
    const float* wr = w + (size_t)o * FC1_OUT;
    float acc = 0.f;
#pragma unroll 8
    for (int k = lane; k < FC1_OUT; k += 32)
        acc += sr[k] * wr[k];
#pragma unroll
    for (int off = 16; off; off >>= 1)
        acc += __shfl_down_sync(0xFFFFFFFFu, acc, off);
    if (lane == 0)
        g_fc2out[row * FC2_OUT + o] = acc;
}

// ---------------- fc2 LIF chain -> final c2 ----------------
__global__ void fc2_chain_kernel(const float* __restrict__ fc2_b,
                                 float* __restrict__ c2)
{
    int idx = threadIdx.x;
    if (idx >= B * FC2_OUT) return;
    int b = idx / FC2_OUT, o = idx % FC2_OUT;
    float bias = fc2_b[o];
    float m = 0.f;
#pragma unroll
    for (int t = 0; t < TSTEPS; ++t) {
        m += g_fc2out[(t * B + b) * FC2_OUT + o] + bias;
        float sp = (m >= 1.f) ? 1.f : 0.f;
        m -= sp;
    }
    c2[idx] = m;
}

// ---------------- host launcher ----------------
extern "C" void kernel_launch(void* const* d_in, const int* in_sizes, int n_in,
                              void* d_out, int out_size)
{
    const float* X       = (const float*)d_in[0];
    const float* conv1_w = (const float*)d_in[1];
    const float* conv1_b = (const float*)d_in[2];
    const float* conv2_w = (const float*)d_in[3];
    const float* conv2_b = (const float*)d_in[4];
    const float* conv3_w = (const float*)d_in[5];
    const float* conv3_b = (const float*)d_in[6];
    const float* fc1_w   = (const float*)d_in[7];
    const float* fc1_b   = (const float*)d_in[8];
    const float* fc2_w   = (const float*)d_in[9];
    const float* fc2_b   = (const float*)d_in[10];
    const float* mask_f1 = (const float*)d_in[11];
    const float* mask_f2 = (const float*)d_in[12];
    const float* mask_c1 = (const float*)d_in[13];

    float* c2 = (float*)d_out;

    float *conv1out, *s1t, *conv2out, *s2p, *conv3out;
    cudaGetSymbolAddress((void**)&conv1out, g_conv1out);
    cudaGetSymbolAddress((void**)&s1t,      g_s1t);
    cudaGetSymbolAddress((void**)&conv2out, g_conv2out_all);
    cudaGetSymbolAddress((void**)&s2p,      g_s2p_all);
    cudaGetSymbolAddress((void**)&conv3out, g_conv3out_all);

    // layer 1: conv once, LIF over all timesteps once
    conv3x3_pipe<3, H1, 1, 1><<<dim3(C1_OUT / 8, B), 256>>>(X, conv1_w, conv1_b, conv1out, C1_OUT);
    lif1_all_kernel<<<(N1 + 255) / 256, 256>>>(mask_f1);

    // layer 2: all 8 timesteps batched into one conv launch, then reg-chained LIF+pool
    conv3x3_pipe<C1_OUT, H1, 1, 4><<<dim3(C2_OUT / 8, ROWS), 256>>>(
        s1t, conv2_w, conv2_b, conv2out, C2_OUT);
    lif2pool_all_kernel<<<(B * C2_OUT * H3 * H3 + 255) / 256, 256>>>();

    // layer 3: batched conv + chained LIF+mask+pool
    conv3x3_pipe<C2_OUT, H3, 2, 4><<<dim3(C2_OUT / 8, ROWS / 2), 128>>>(
        s2p, conv3_w, conv3_b, conv3out, C2_OUT);
    lif3maskpool_all_kernel<<<(B * C2_OUT * 8 * 8 + 255) / 256, 256>>>(mask_f2);

    // fc1: one batched GEMM (k-split), then chained reduce+LIF+mask
    fc1_gemm_kernel<<<dim3(FC1_OUT / 64, ROWS / 64, KSPLIT), 256>>>(fc1_w);
    fc1_chain_kernel<<<(B * FC1_OUT + 255) / 256, 256>>>(fc1_b, mask_c1);

    // fc2: batched dot products, then final membrane chain into d_out
    fc2_all_kernel<<<(ROWS * FC2_OUT * 32 + 255) / 256, 256>>>(fc2_w);
    fc2_chain_kernel<<<1, 512>>>(fc2_b, c2);
}